// round 15
// baseline (speedup 1.0000x reference)
#include <cuda_runtime.h>
#include <cuda_fp16.h>
#include <math_constants.h>
#include <cstdint>
#include <cstring>

#define D_DIM   256
#define CAP     32
#define MARGIN  4.0e-4f            // dist units (pass2 prune)
#define MS      0.1024f            // scaled-dot margin = 512 * MARGIN / 2
#define MAXBT   65536
#define MAXCODE 8192
#define BATCH   8

// ---------------- static device scratch (no allocations) ------------------
__device__ float    g_en[MAXCODE];
__device__ double   g_loss;
__device__ int      g_ctr;
__device__ int      g_rowmax[MAXBT];                          // ordered-int float
__device__ uint32_t g_eh2[(size_t)(MAXCODE / 128) * 16384];   // [chunk][kp][code] half2
__device__ float    g_cs[(size_t)MAXBT * CAP];
__device__ int      g_ci[(size_t)MAXBT * CAP];
__device__ int      g_cn[MAXBT];

// ---------------- helpers ---------------------------------------------------
__device__ __forceinline__ uint32_t smem_u32(const void* p) {
    uint32_t r;
    asm("{ .reg .u64 t; cvta.to.shared.u64 t, %1; cvt.u32.u64 %0, t; }" : "=r"(r) : "l"(p));
    return r;
}
__device__ __forceinline__ void cp16(uint32_t dst, const void* src) {
    asm volatile("cp.async.cg.shared.global [%0], [%1], 16;" :: "r"(dst), "l"(src) : "memory");
}
#define CP_COMMIT() asm volatile("cp.async.commit_group;" ::: "memory")
#define CP_WAIT(n)  asm volatile("cp.async.wait_group %0;" :: "n"(n) : "memory")

__device__ __forceinline__ __half2 u2h(uint32_t u) {
    __half2 h; memcpy(&h, &u, 4); return h;
}
// order-preserving float<->int for signed atomicMax
__device__ __forceinline__ int encf(float f) {
    int i = __float_as_int(f);
    return (i < 0) ? (i ^ 0x7fffffff) : i;
}
__device__ __forceinline__ float decf(int i) {
    int j = (i < 0) ? (i ^ 0x7fffffff) : i;
    return __int_as_float(j);
}

// ---------------- K0: zero --------------------------------------------------
__global__ void vq_zero() {
    int i = blockIdx.x * blockDim.x + threadIdx.x;
    if (i == 0) { g_loss = 0.0; g_ctr = 0; }
    if (i < MAXBT) { g_cn[i] = 0; g_rowmax[i] = 0x80000000; }
}

// ---------------- K1: ||e||^2, round-1 exact formula (proven) ---------------
__global__ void vq_enorm(const float* __restrict__ emb, int ncodes) {
    int code = (blockIdx.x * blockDim.x + threadIdx.x) >> 5;
    int lane = threadIdx.x & 31;
    if (code >= ncodes) return;
    const float* e = emb + (size_t)code * D_DIM;
    float s = 0.f;
#pragma unroll
    for (int t = 0; t < 8; ++t) {
        float v = e[lane + t * 32];
        s = __fadd_rn(s, __fmul_rn(v, v));
    }
#pragma unroll
    for (int o = 16; o; o >>= 1) s = __fadd_rn(s, __shfl_xor_sync(0xffffffffu, s, o));
    if (lane == 0) g_en[code] = s;
}

// ---------------- K2: stage emb as k-pair half2, scaled by 512 --------------
// word idx = chunk*16384 + kp*128 + (code & 127);  chunk = 128 codes, kp = 0..127
__global__ void vq_pack(const float* __restrict__ emb, int ncodes) {
    int idx = blockIdx.x * blockDim.x + threadIdx.x;
    int code = idx >> 5, lane = idx & 31;
    if (code >= ncodes) return;
    const float* e = emb + (size_t)code * D_DIM;
    int chunk = code >> 7, cl = code & 127;
    uint32_t* dst = g_eh2 + (size_t)chunk * 16384 + cl;
#pragma unroll
    for (int t = 0; t < 4; ++t) {
        int kp = lane + t * 32;
        __half2 h = __floats2half2_rn(e[2 * kp] * 512.f, e[2 * kp + 1] * 512.f);
        uint32_t w; memcpy(&w, &h, 4);
        dst[(size_t)kp * 128] = w;
    }
}

// ---------------- K3: persistent HFMA2 k-pair scoring, 4 CTAs/SM ------------
// unit = tile(64 rows) * 64 + chunk(128 codes); 8 k-slices (16 kp) per unit
// smem (words): xs[128][64] half2 (x loads are warp-uniform -> no padding) |
//               es[3][16][128] triple buffer | u0
#define XS_STR 64
#define XS_W   (128 * XS_STR)             // 8192 words
#define SLW    2048                       // slice words: 16 kp * 128 codes
#define ES_W   (3 * SLW)                  // 6144 words
#define SMEM1  ((XS_W + ES_W + 8) * 4)    // 57,376 B -> 4 CTAs/SM

__global__ void __launch_bounds__(256, 4)
vq_pass1(const float* __restrict__ x, int BT, int ncodes, int nunits)
{
    extern __shared__ uint32_t sw[];
    uint32_t* xs   = sw;                     // [kp][row] half2 (k-pair)
    uint32_t* es   = sw + XS_W;              // [3][16 kp][128 codes]
    int*      s_u0 = (int*)(sw + XS_W + ES_W);
    const uint32_t es_b = smem_u32(es);
    const int tid = threadIdx.x, wid = tid >> 5, lane = tid & 31;

    int cur_tile = -1;

    __half2 acc[8][4];
#pragma unroll
    for (int i = 0; i < 8; ++i)
#pragma unroll
        for (int j = 0; j < 4; ++j) acc[i][j] = __floats2half2_rn(0.f, 0.f);

    for (;;) {
        if (tid == 0) *s_u0 = atomicAdd(&g_ctr, BATCH);
        __syncthreads();
        const int u0 = *s_u0;
        __syncthreads();
        if (u0 >= nunits) break;
        const int nb = min(BATCH, nunits - u0);
        const int ns = nb * 8;               // 16-kp slices

        // prologue: slices 0,1 -> buffers 0,1 (each 8 KB; 32 B per thread)
#pragma unroll
        for (int c = 0; c < 2; ++c) {
            if (c < ns) {
                const int uu = u0 + (c >> 3);
                const uint32_t* src = g_eh2 + (size_t)(uu & 63) * 16384
                                    + (size_t)(c & 7) * SLW + tid * 8;
                uint32_t dst = es_b + (uint32_t)(c * SLW + tid * 8) * 4;
                cp16(dst, src);
                cp16(dst + 16, src + 4);
            }
            CP_COMMIT();
        }

        for (int s = 0; s < ns; ++s) {
            const int buf = s % 3;
            const int u = u0 + (s >> 3);
            if (s + 1 < ns) { CP_WAIT(1); } else { CP_WAIT(0); }
            __syncthreads();     // cp(s) landed; everyone done with slice s-1

            // prefetch slice s+2 into buf (s+2)%3 == (s-1)%3 (freed by the sync)
            if (s + 2 < ns) {
                const int uu = u0 + ((s + 2) >> 3);
                const uint32_t* src = g_eh2 + (size_t)(uu & 63) * 16384
                                    + (size_t)((s + 2) & 7) * SLW + tid * 8;
                uint32_t dst = es_b + (uint32_t)(((s + 2) % 3) * SLW + tid * 8) * 4;
                cp16(dst, src);
                cp16(dst + 16, src + 4);
                CP_COMMIT();
            }

            if ((s & 7) == 0) {          // unit boundary: tile change?
                const int tile = u >> 6;
                if (tile != cur_tile) {
                    const int row0 = tile * 64;
                    for (int p = tid; p < 64 * 128; p += 256) {
                        int r = p >> 7, kp = p & 127, gr = row0 + r;
                        float2 v = (gr < BT) ? *(const float2*)(x + (size_t)gr * D_DIM + kp * 2)
                                             : make_float2(0.f, 0.f);
                        __half2 h = __floats2half2_rn(v.x, v.y);
                        uint32_t w; memcpy(&w, &h, 4);
                        xs[kp * XS_STR + r] = w;
                    }
                    cur_tile = tile;
                    __syncthreads();
                }
            }

            const uint32_t* eb = es + buf * SLW + lane * 4;
            const uint32_t* xb = xs + ((s & 7) * 16) * XS_STR + wid * 8;  // warp-uniform
#pragma unroll 4
            for (int kk = 0; kk < 16; ++kk) {
                uint4 aw0 = *(const uint4*)(xb + kk * XS_STR);       // rows w*8..+3
                uint4 aw1 = *(const uint4*)(xb + kk * XS_STR + 4);   // rows w*8+4..+7
                uint4 bv  = *(const uint4*)(eb + kk * 128);          // 4 codes
                __half2 a[8], b[4];
                a[0] = u2h(aw0.x); a[1] = u2h(aw0.y); a[2] = u2h(aw0.z); a[3] = u2h(aw0.w);
                a[4] = u2h(aw1.x); a[5] = u2h(aw1.y); a[6] = u2h(aw1.z); a[7] = u2h(aw1.w);
                b[0] = u2h(bv.x);  b[1] = u2h(bv.y);  b[2] = u2h(bv.z);  b[3] = u2h(bv.w);
#pragma unroll
                for (int i = 0; i < 8; ++i) {
                    acc[i][0] = __hfma2(a[i], b[0], acc[i][0]);
                    acc[i][1] = __hfma2(a[i], b[1], acc[i][1]);
                    acc[i][2] = __hfma2(a[i], b[2], acc[i][2]);
                    acc[i][3] = __hfma2(a[i], b[3], acc[i][3]);
                }
            }

            if ((s & 7) == 7) {          // unit epilogue: 128 codes scored (warp-local)
                const int chunk = u & 63;
                const int wrow  = (u >> 6) * 64 + wid * 8;
                const bool rowok = wrow < BT;
                float m[8];
#pragma unroll
                for (int i = 0; i < 8; ++i) {
                    float mm = -CUDART_INF_F;
#pragma unroll
                    for (int j = 0; j < 4; ++j) {
                        float2 f = __half22float2(acc[i][j]);
                        mm = fmaxf(mm, f.x + f.y);
                    }
                    m[i] = mm;
                }
#pragma unroll
                for (int o = 16; o; o >>= 1) {
#pragma unroll
                    for (int i = 0; i < 8; ++i)
                        m[i] = fmaxf(m[i], __shfl_xor_sync(0xffffffffu, m[i], o));
                }
                float thl = 0.f;
                if (lane < 8 && rowok) {
                    int old = atomicMax(&g_rowmax[wrow + lane], encf(m[lane]));
                    thl = fmaxf(m[lane], decf(old)) - MS;
                }
#pragma unroll
                for (int i = 0; i < 8; ++i) {
                    const float th = __shfl_sync(0xffffffffu, thl, i);
                    if (rowok) {
                        const int grow = wrow + i;
#pragma unroll
                        for (int j = 0; j < 4; ++j) {
                            float2 f = __half22float2(acc[i][j]);
                            float v = f.x + f.y;
                            if (v >= th) {
                                int code = chunk * 128 + lane * 4 + j;
                                int pos = atomicAdd(&g_cn[grow], 1);
                                if (pos < CAP) {
                                    g_cs[(size_t)grow * CAP + pos] = -v * (1.f / 256.f);
                                    g_ci[(size_t)grow * CAP + pos] = code;
                                }
                            }
                        }
                    }
                    acc[i][0] = __floats2half2_rn(0.f, 0.f);
                    acc[i][1] = __floats2half2_rn(0.f, 0.f);
                    acc[i][2] = __floats2half2_rn(0.f, 0.f);
                    acc[i][3] = __floats2half2_rn(0.f, 0.f);
                }
            }
        }
    }
}

// ---------------- K4: exact fp32 recheck (round-1 arithmetic) + epilogue ----
__global__ void __launch_bounds__(256)
vq_pass2(const float* __restrict__ x, const float* __restrict__ emb,
         float* __restrict__ y_out, float* __restrict__ idx_out,
         int BT, int ncodes)
{
    __shared__ float  SX[8][256];
    __shared__ double wl[8];
    const int tid = threadIdx.x, w = tid >> 5, lane = tid & 31;
    const int r = blockIdx.x * 8 + w;
    float lsum = 0.f;

    if (r < BT) {
        {
            float4 a = *(const float4*)(x + (size_t)r * D_DIM + lane * 8);
            float4 b = *(const float4*)(x + (size_t)r * D_DIM + lane * 8 + 4);
            *(float4*)(&SX[w][lane * 8]) = a;
            *(float4*)(&SX[w][lane * 8 + 4]) = b;
        }
        __syncwarp();

        const int cntraw = g_cn[r];
        int winner;

        if (cntraw > CAP) {
            // overflow fallback: full exact scan (round-1 arithmetic per code)
            float x2 = 0.f;
            for (int k = 0; k < D_DIM; ++k) {
                float xv = SX[w][k];
                x2 = __fadd_rn(x2, __fmul_rn(xv, xv));
            }
            float bd = CUDART_INF_F; int bc = 0x7fffffff;
            for (int c = lane; c < ncodes; c += 32) {
                const float* e = emb + (size_t)c * D_DIM;
                float acc = 0.f;
                for (int k = 0; k < D_DIM; ++k)
                    acc = __fmaf_rn(SX[w][k], __ldg(e + k), acc);
                float d = __fadd_rn(__fsub_rn(x2, __fmul_rn(2.0f, acc)), g_en[c]);
                if (d < bd) { bd = d; bc = c; }
            }
#pragma unroll
            for (int o = 16; o; o >>= 1) {
                float od = __shfl_xor_sync(0xffffffffu, bd, o);
                int   oc = __shfl_xor_sync(0xffffffffu, bc, o);
                if (od < bd || (od == bd && oc < bc)) { bd = od; bc = oc; }
            }
            winner = bc;
        } else {
            const int cnt = cntraw;
            float s = (lane < cnt) ? g_cs[(size_t)r * CAP + lane] : CUDART_INF_F;
            int   c = (lane < cnt) ? g_ci[(size_t)r * CAP + lane] : 0x7fffffff;
            float smin = s;
#pragma unroll
            for (int o = 16; o; o >>= 1) smin = fminf(smin, __shfl_xor_sync(0xffffffffu, smin, o));
            const bool surv = s <= smin + MARGIN;
            const int nsurv = __popc(__ballot_sync(0xffffffffu, surv));

            float d = CUDART_INF_F; int cid = 0x7fffffff;
            if (nsurv == 1) {
                if (surv) { d = 0.f; cid = c; }
            } else if (surv) {
                const float* e = emb + (size_t)c * D_DIM;
                float acc = 0.f, x2 = 0.f;
#pragma unroll 8
                for (int k = 0; k < D_DIM; ++k) {
                    float xv = SX[w][k];
                    x2  = __fadd_rn(x2, __fmul_rn(xv, xv));
                    acc = __fmaf_rn(xv, __ldg(e + k), acc);
                }
                d = __fadd_rn(__fsub_rn(x2, __fmul_rn(2.0f, acc)), g_en[c]);
                cid = c;
            }
#pragma unroll
            for (int o = 16; o; o >>= 1) {
                float od = __shfl_xor_sync(0xffffffffu, d, o);
                int   oc = __shfl_xor_sync(0xffffffffu, cid, o);
                if (od < d || (od == d && oc < cid)) { d = od; cid = oc; }
            }
            winner = cid;
        }

        if (lane == 0 && idx_out != nullptr) idx_out[r] = (float)winner;

        const float* q = emb + (size_t)winner * D_DIM;
        float4 qa = *(const float4*)(q + lane * 8);
        float4 qb = *(const float4*)(q + lane * 8 + 4);
        float qv[8], xv[8], yv[8];
        *(float4*)(qv) = qa; *(float4*)(qv + 4) = qb;
        *(float4*)(xv) = *(float4*)(&SX[w][lane * 8]);
        *(float4*)(xv + 4) = *(float4*)(&SX[w][lane * 8 + 4]);
#pragma unroll
        for (int t = 0; t < 8; ++t) {
            float df = __fsub_rn(qv[t], xv[t]);
            yv[t] = __fadd_rn(xv[t], df);
            lsum = __fmaf_rn(df, df, lsum);
        }
        *(float4*)(y_out + (size_t)r * D_DIM + lane * 8) = *(float4*)(yv);
        *(float4*)(y_out + (size_t)r * D_DIM + lane * 8 + 4) = *(float4*)(yv + 4);
    }
#pragma unroll
    for (int o = 16; o; o >>= 1) lsum += __shfl_xor_sync(0xffffffffu, lsum, o);
    if (lane == 0) wl[w] = (double)lsum;
    __syncthreads();
    if (tid == 0) {
        double t = 0.0;
#pragma unroll
        for (int i = 0; i < 8; ++i) t += wl[i];
        atomicAdd(&g_loss, t);
    }
}

__global__ void vq_fin(float* __restrict__ loss_out, double inv_n) {
    loss_out[0] = (float)(g_loss * inv_n);
}

// --------------------------------- launch -----------------------------------
extern "C" void kernel_launch(void* const* d_in, const int* in_sizes, int n_in,
                              void* d_out, int out_size)
{
    int xi = 0, ei = 1;
    if (n_in >= 2 && in_sizes[1] > in_sizes[0]) { xi = 1; ei = 0; }
    const float* x   = (const float*)d_in[xi];
    const float* emb = (const float*)d_in[ei];
    const int BT     = in_sizes[xi] / D_DIM;
    const int ncodes = in_sizes[ei] / D_DIM;

    float* out = (float*)d_out;
    const long long yN = (long long)BT * D_DIM;
    float* idxp = ((long long)out_size >= yN + BT) ? out + yN : nullptr;
    const bool has_loss = ((long long)out_size >= yN + BT + 1);

    const int ntiles = (BT + 63) / 64;
    const int nunits = ntiles * (ncodes / 128);

    cudaFuncSetAttribute((const void*)vq_pass1,
                         cudaFuncAttributeMaxDynamicSharedMemorySize, SMEM1);

    vq_zero<<<256, 256>>>();
    vq_enorm<<<(ncodes * 32 + 255) / 256, 256>>>(emb, ncodes);
    vq_pack<<<(ncodes * 32 + 255) / 256, 256>>>(emb, ncodes);
    vq_pass1<<<592, 256, SMEM1>>>(x, BT, ncodes, nunits);
    vq_pass2<<<(BT + 7) / 8, 256>>>(x, emb, out, idxp, BT, ncodes);
    if (has_loss)
        vq_fin<<<1, 1>>>(out + yN + BT, 1.0 / ((double)BT * (double)D_DIM));
}

// round 16
// speedup vs baseline: 1.0984x; 1.0984x over previous
#include <cuda_runtime.h>
#include <cuda_fp16.h>
#include <math_constants.h>
#include <cstdint>
#include <cstring>

#define D_DIM   256
#define CAP     32
#define MARGIN  4.0e-4f            // dist units (pass2 prune)
#define MS      0.1024f            // scaled-dot margin = 512 * MARGIN / 2
#define MAXBT   65536
#define MAXCODE 8192
#define BATCH   16

// ---------------- static device scratch (no allocations) ------------------
__device__ float    g_en[MAXCODE];
__device__ double   g_loss;
__device__ int      g_ctr;
__device__ int      g_rowmax[MAXBT];                          // ordered-int float
__device__ uint32_t g_eh2[(size_t)(MAXCODE / 128) * 16384];   // [chunk][kp][code] half2
__device__ float    g_cs[(size_t)MAXBT * CAP];
__device__ int      g_ci[(size_t)MAXBT * CAP];
__device__ int      g_cn[MAXBT];

// ---------------- helpers ---------------------------------------------------
__device__ __forceinline__ uint32_t smem_u32(const void* p) {
    uint32_t r;
    asm("{ .reg .u64 t; cvta.to.shared.u64 t, %1; cvt.u32.u64 %0, t; }" : "=r"(r) : "l"(p));
    return r;
}
__device__ __forceinline__ void cp16(uint32_t dst, const void* src) {
    asm volatile("cp.async.cg.shared.global [%0], [%1], 16;" :: "r"(dst), "l"(src) : "memory");
}
#define CP_COMMIT() asm volatile("cp.async.commit_group;" ::: "memory")
#define CP_WAIT(n)  asm volatile("cp.async.wait_group %0;" :: "n"(n) : "memory")

__device__ __forceinline__ __half2 u2h(uint32_t u) {
    __half2 h; memcpy(&h, &u, 4); return h;
}
// order-preserving float<->int for signed atomicMax
__device__ __forceinline__ int encf(float f) {
    int i = __float_as_int(f);
    return (i < 0) ? (i ^ 0x7fffffff) : i;
}
__device__ __forceinline__ float decf(int i) {
    int j = (i < 0) ? (i ^ 0x7fffffff) : i;
    return __int_as_float(j);
}

// ---------------- K0: zero --------------------------------------------------
__global__ void vq_zero() {
    int i = blockIdx.x * blockDim.x + threadIdx.x;
    if (i == 0) { g_loss = 0.0; g_ctr = 0; }
    if (i < MAXBT) { g_cn[i] = 0; g_rowmax[i] = 0x80000000; }
}

// ---------------- K1: ||e||^2, round-1 exact formula (proven) ---------------
__global__ void vq_enorm(const float* __restrict__ emb, int ncodes) {
    int code = (blockIdx.x * blockDim.x + threadIdx.x) >> 5;
    int lane = threadIdx.x & 31;
    if (code >= ncodes) return;
    const float* e = emb + (size_t)code * D_DIM;
    float s = 0.f;
#pragma unroll
    for (int t = 0; t < 8; ++t) {
        float v = e[lane + t * 32];
        s = __fadd_rn(s, __fmul_rn(v, v));
    }
#pragma unroll
    for (int o = 16; o; o >>= 1) s = __fadd_rn(s, __shfl_xor_sync(0xffffffffu, s, o));
    if (lane == 0) g_en[code] = s;
}

// ---------------- K2: stage emb as k-pair half2, scaled by 512 --------------
// word idx = chunk*16384 + kp*128 + (code & 127);  chunk = 128 codes, kp = 0..127
__global__ void vq_pack(const float* __restrict__ emb, int ncodes) {
    int idx = blockIdx.x * blockDim.x + threadIdx.x;
    int code = idx >> 5, lane = idx & 31;
    if (code >= ncodes) return;
    const float* e = emb + (size_t)code * D_DIM;
    int chunk = code >> 7, cl = code & 127;
    uint32_t* dst = g_eh2 + (size_t)chunk * 16384 + cl;
#pragma unroll
    for (int t = 0; t < 4; ++t) {
        int kp = lane + t * 32;
        __half2 h = __floats2half2_rn(e[2 * kp] * 512.f, e[2 * kp + 1] * 512.f);
        uint32_t w; memcpy(&w, &h, 4);
        dst[(size_t)kp * 128] = w;
    }
}

// ---------------- K3: persistent HFMA2 k-pair scoring, 3 CTAs/SM ------------
// unit = tile(64 rows) * 64 + chunk(128 codes); 4 k-slices (32 kp) per unit
// smem (words): xs[128][68] half2 (64 rows + 4 pad, 16B-aligned stride) |
//               es[2][32][128] | u0
#define XS_STR 68
#define XS_W   (128 * XS_STR)             // 8704 words
#define ES_W   8192
#define SMEM1  ((XS_W + ES_W + 8) * 4)    // 67,616 B -> 3 CTAs/SM

__global__ void __launch_bounds__(256, 3)
vq_pass1(const float* __restrict__ x, int BT, int ncodes, int nunits)
{
    extern __shared__ uint32_t sw[];
    uint32_t* xs   = sw;                     // [kp][row] half2 (k-pair)
    uint32_t* es   = sw + XS_W;              // [2][32 kp][128 codes]
    int*      s_u0 = (int*)(sw + XS_W + ES_W);
    const uint32_t es_b = smem_u32(es);
    const int tid = threadIdx.x, wid = tid >> 5, lane = tid & 31;

    int cur_tile = -1;

    __half2 acc[8][4];
#pragma unroll
    for (int i = 0; i < 8; ++i)
#pragma unroll
        for (int j = 0; j < 4; ++j) acc[i][j] = __floats2half2_rn(0.f, 0.f);

    for (;;) {
        if (tid == 0) *s_u0 = atomicAdd(&g_ctr, BATCH);
        __syncthreads();
        const int u0 = *s_u0;
        __syncthreads();
        if (u0 >= nunits) break;
        const int nb = min(BATCH, nunits - u0);
        const int ns = nb * 4;

        // prologue: slices 0,1 of this batch
#pragma unroll
        for (int c = 0; c < 2; ++c) {
            if (c < ns) {
                const int uu = u0 + (c >> 2);
                const uint32_t* src = g_eh2 + (size_t)(uu & 63) * 16384
                                    + (size_t)(c & 3) * 4096 + tid * 16;
                uint32_t dst = es_b + (uint32_t)((c & 1) * 4096 + tid * 16) * 4;
#pragma unroll
                for (int i = 0; i < 4; ++i) cp16(dst + i * 16, src + i * 4);
            }
            CP_COMMIT();
        }

        for (int s = 0; s < ns; ++s) {
            const int buf = s & 1;
            const int u = u0 + (s >> 2);
            if (s + 1 < ns) { CP_WAIT(1); } else { CP_WAIT(0); }
            __syncthreads();

            if ((s & 3) == 0) {          // unit boundary: tile change?
                const int tile = u >> 6;
                if (tile != cur_tile) {
                    const int row0 = tile * 64;
                    for (int p = tid; p < 64 * 128; p += 256) {
                        int r = p >> 7, kp = p & 127, gr = row0 + r;
                        float2 v = (gr < BT) ? *(const float2*)(x + (size_t)gr * D_DIM + kp * 2)
                                             : make_float2(0.f, 0.f);
                        __half2 h = __floats2half2_rn(v.x, v.y);
                        uint32_t w; memcpy(&w, &h, 4);
                        xs[kp * XS_STR + r] = w;
                    }
                    cur_tile = tile;
                    __syncthreads();
                }
            }

            const uint32_t* eb = es + buf * 4096 + lane * 4;
            const uint32_t* xb = xs + (s & 3) * (32 * XS_STR) + wid * 8;   // warp-uniform
#pragma unroll 8
            for (int kk = 0; kk < 32; ++kk) {
                uint4 aw0 = *(const uint4*)(xb + kk * XS_STR);       // rows w*8..+3
                uint4 aw1 = *(const uint4*)(xb + kk * XS_STR + 4);   // rows w*8+4..+7
                uint4 bv  = *(const uint4*)(eb + kk * 128);          // 4 codes
                __half2 a[8], b[4];
                a[0] = u2h(aw0.x); a[1] = u2h(aw0.y); a[2] = u2h(aw0.z); a[3] = u2h(aw0.w);
                a[4] = u2h(aw1.x); a[5] = u2h(aw1.y); a[6] = u2h(aw1.z); a[7] = u2h(aw1.w);
                b[0] = u2h(bv.x);  b[1] = u2h(bv.y);  b[2] = u2h(bv.z);  b[3] = u2h(bv.w);
#pragma unroll
                for (int i = 0; i < 8; ++i) {
                    acc[i][0] = __hfma2(a[i], b[0], acc[i][0]);
                    acc[i][1] = __hfma2(a[i], b[1], acc[i][1]);
                    acc[i][2] = __hfma2(a[i], b[2], acc[i][2]);
                    acc[i][3] = __hfma2(a[i], b[3], acc[i][3]);
                }
            }
            __syncthreads();             // everyone done reading buf

            // prefetch first: overlaps with the (register-only) epilogue below
            if (s + 2 < ns) {
                const int uu = u0 + ((s + 2) >> 2);
                const uint32_t* src = g_eh2 + (size_t)(uu & 63) * 16384
                                    + (size_t)((s + 2) & 3) * 4096 + tid * 16;
                uint32_t dst = es_b + (uint32_t)(buf * 4096 + tid * 16) * 4;
#pragma unroll
                for (int i = 0; i < 4; ++i) cp16(dst + i * 16, src + i * 4);
                CP_COMMIT();
            }

            if ((s & 3) == 3) {          // unit epilogue: 128 codes scored
                const int chunk = u & 63;
                const int wrow  = (u >> 6) * 64 + wid * 8;
                const bool rowok = wrow < BT;
                float m[8];
#pragma unroll
                for (int i = 0; i < 8; ++i) {
                    float mm = -CUDART_INF_F;
#pragma unroll
                    for (int j = 0; j < 4; ++j) {
                        float2 f = __half22float2(acc[i][j]);
                        mm = fmaxf(mm, f.x + f.y);
                    }
                    m[i] = mm;
                }
#pragma unroll
                for (int o = 16; o; o >>= 1) {
#pragma unroll
                    for (int i = 0; i < 8; ++i)
                        m[i] = fmaxf(m[i], __shfl_xor_sync(0xffffffffu, m[i], o));
                }
                float thl = 0.f;
                if (lane < 8 && rowok) {
                    int old = atomicMax(&g_rowmax[wrow + lane], encf(m[lane]));
                    thl = fmaxf(m[lane], decf(old)) - MS;
                }
#pragma unroll
                for (int i = 0; i < 8; ++i) {
                    const float th = __shfl_sync(0xffffffffu, thl, i);
                    if (rowok) {
                        const int grow = wrow + i;
#pragma unroll
                        for (int j = 0; j < 4; ++j) {
                            float2 f = __half22float2(acc[i][j]);
                            float v = f.x + f.y;
                            if (v >= th) {
                                int code = chunk * 128 + lane * 4 + j;
                                int pos = atomicAdd(&g_cn[grow], 1);
                                if (pos < CAP) {
                                    g_cs[(size_t)grow * CAP + pos] = -v * (1.f / 256.f);
                                    g_ci[(size_t)grow * CAP + pos] = code;
                                }
                            }
                        }
                    }
                    acc[i][0] = __floats2half2_rn(0.f, 0.f);
                    acc[i][1] = __floats2half2_rn(0.f, 0.f);
                    acc[i][2] = __floats2half2_rn(0.f, 0.f);
                    acc[i][3] = __floats2half2_rn(0.f, 0.f);
                }
            }
        }
    }
}

// ---------------- K4: exact fp32 recheck (round-1 arithmetic) + epilogue ----
__global__ void __launch_bounds__(256)
vq_pass2(const float* __restrict__ x, const float* __restrict__ emb,
         float* __restrict__ y_out, float* __restrict__ idx_out,
         int BT, int ncodes)
{
    __shared__ float  SX[8][256];
    __shared__ double wl[8];
    const int tid = threadIdx.x, w = tid >> 5, lane = tid & 31;
    const int r = blockIdx.x * 8 + w;
    float lsum = 0.f;

    if (r < BT) {
        {
            float4 a = *(const float4*)(x + (size_t)r * D_DIM + lane * 8);
            float4 b = *(const float4*)(x + (size_t)r * D_DIM + lane * 8 + 4);
            *(float4*)(&SX[w][lane * 8]) = a;
            *(float4*)(&SX[w][lane * 8 + 4]) = b;
        }
        __syncwarp();

        const int cntraw = g_cn[r];
        int winner;

        if (cntraw > CAP) {
            // overflow fallback: full exact scan (round-1 arithmetic per code)
            float x2 = 0.f;
            for (int k = 0; k < D_DIM; ++k) {
                float xv = SX[w][k];
                x2 = __fadd_rn(x2, __fmul_rn(xv, xv));
            }
            float bd = CUDART_INF_F; int bc = 0x7fffffff;
            for (int c = lane; c < ncodes; c += 32) {
                const float* e = emb + (size_t)c * D_DIM;
                float acc = 0.f;
                for (int k = 0; k < D_DIM; ++k)
                    acc = __fmaf_rn(SX[w][k], __ldg(e + k), acc);
                float d = __fadd_rn(__fsub_rn(x2, __fmul_rn(2.0f, acc)), g_en[c]);
                if (d < bd) { bd = d; bc = c; }
            }
#pragma unroll
            for (int o = 16; o; o >>= 1) {
                float od = __shfl_xor_sync(0xffffffffu, bd, o);
                int   oc = __shfl_xor_sync(0xffffffffu, bc, o);
                if (od < bd || (od == bd && oc < bc)) { bd = od; bc = oc; }
            }
            winner = bc;
        } else {
            const int cnt = cntraw;
            float s = (lane < cnt) ? g_cs[(size_t)r * CAP + lane] : CUDART_INF_F;
            int   c = (lane < cnt) ? g_ci[(size_t)r * CAP + lane] : 0x7fffffff;
            float smin = s;
#pragma unroll
            for (int o = 16; o; o >>= 1) smin = fminf(smin, __shfl_xor_sync(0xffffffffu, smin, o));
            const bool surv = s <= smin + MARGIN;
            const int nsurv = __popc(__ballot_sync(0xffffffffu, surv));

            float d = CUDART_INF_F; int cid = 0x7fffffff;
            if (nsurv == 1) {
                if (surv) { d = 0.f; cid = c; }
            } else if (surv) {
                const float* e = emb + (size_t)c * D_DIM;
                float acc = 0.f, x2 = 0.f;
#pragma unroll 8
                for (int k = 0; k < D_DIM; ++k) {
                    float xv = SX[w][k];
                    x2  = __fadd_rn(x2, __fmul_rn(xv, xv));
                    acc = __fmaf_rn(xv, __ldg(e + k), acc);
                }
                d = __fadd_rn(__fsub_rn(x2, __fmul_rn(2.0f, acc)), g_en[c]);
                cid = c;
            }
#pragma unroll
            for (int o = 16; o; o >>= 1) {
                float od = __shfl_xor_sync(0xffffffffu, d, o);
                int   oc = __shfl_xor_sync(0xffffffffu, cid, o);
                if (od < d || (od == d && oc < cid)) { d = od; cid = oc; }
            }
            winner = cid;
        }

        if (lane == 0 && idx_out != nullptr) idx_out[r] = (float)winner;

        const float* q = emb + (size_t)winner * D_DIM;
        float4 qa = *(const float4*)(q + lane * 8);
        float4 qb = *(const float4*)(q + lane * 8 + 4);
        float qv[8], xv[8], yv[8];
        *(float4*)(qv) = qa; *(float4*)(qv + 4) = qb;
        *(float4*)(xv) = *(float4*)(&SX[w][lane * 8]);
        *(float4*)(xv + 4) = *(float4*)(&SX[w][lane * 8 + 4]);
#pragma unroll
        for (int t = 0; t < 8; ++t) {
            float df = __fsub_rn(qv[t], xv[t]);
            yv[t] = __fadd_rn(xv[t], df);
            lsum = __fmaf_rn(df, df, lsum);
        }
        *(float4*)(y_out + (size_t)r * D_DIM + lane * 8) = *(float4*)(yv);
        *(float4*)(y_out + (size_t)r * D_DIM + lane * 8 + 4) = *(float4*)(yv + 4);
    }
#pragma unroll
    for (int o = 16; o; o >>= 1) lsum += __shfl_xor_sync(0xffffffffu, lsum, o);
    if (lane == 0) wl[w] = (double)lsum;
    __syncthreads();
    if (tid == 0) {
        double t = 0.0;
#pragma unroll
        for (int i = 0; i < 8; ++i) t += wl[i];
        atomicAdd(&g_loss, t);
    }
}

__global__ void vq_fin(float* __restrict__ loss_out, double inv_n) {
    loss_out[0] = (float)(g_loss * inv_n);
}

// --------------------------------- launch -----------------------------------
extern "C" void kernel_launch(void* const* d_in, const int* in_sizes, int n_in,
                              void* d_out, int out_size)
{
    int xi = 0, ei = 1;
    if (n_in >= 2 && in_sizes[1] > in_sizes[0]) { xi = 1; ei = 0; }
    const float* x   = (const float*)d_in[xi];
    const float* emb = (const float*)d_in[ei];
    const int BT     = in_sizes[xi] / D_DIM;
    const int ncodes = in_sizes[ei] / D_DIM;

    float* out = (float*)d_out;
    const long long yN = (long long)BT * D_DIM;
    float* idxp = ((long long)out_size >= yN + BT) ? out + yN : nullptr;
    const bool has_loss = ((long long)out_size >= yN + BT + 1);

    const int ntiles = (BT + 63) / 64;
    const int nunits = ntiles * (ncodes / 128);

    cudaFuncSetAttribute((const void*)vq_pass1,
                         cudaFuncAttributeMaxDynamicSharedMemorySize, SMEM1);

    vq_zero<<<256, 256>>>();
    vq_enorm<<<(ncodes * 32 + 255) / 256, 256>>>(emb, ncodes);
    vq_pack<<<(ncodes * 32 + 255) / 256, 256>>>(emb, ncodes);
    vq_pass1<<<444, 256, SMEM1>>>(x, BT, ncodes, nunits);
    vq_pass2<<<(BT + 7) / 8, 256>>>(x, emb, out, idxp, BT, ncodes);
    if (has_loss)
        vq_fin<<<1, 1>>>(out + yN + BT, 1.0 / ((double)BT * (double)D_DIM));
}